// round 13
// baseline (speedup 1.0000x reference)
#include <cuda_runtime.h>
#include <cuda_fp16.h>
#include <math.h>
#include <stdint.h>

#define BB 512
#define NXD 64
#define NYD 64
#define HID 256

// ---------------- device scratch ---------------------------------------------
__device__ __align__(16) uint32_t g_xph[BB * 128];   // fp16 pairs: b1 + X@W1[:64]
__device__ __align__(16) uint32_t g_yph[BB * 128];   // fp16 pairs: Y@W1[64:]
__device__ __align__(16) uint32_t g_w2h[HID * 128];  // W2^T fp16 pairs [n][kp]
__device__ __align__(16) float g_rowpart[BB * 64];   // [row i][bx] sum of exp
__device__ float g_diag[BB];

// ---------------- helpers ----------------------------------------------------
__device__ __forceinline__ uint32_t smem_u32(const void* p) {
    uint32_t a;
    asm("{ .reg .u64 t; cvta.to.shared.u64 t, %1; cvt.u32.u64 %0, t; }"
        : "=r"(a) : "l"(p));
    return a;
}

__device__ __forceinline__ void mma_f16(float* c, const uint32_t* a,
                                        const uint32_t* b) {
    asm volatile(
        "mma.sync.aligned.m16n8k16.row.col.f32.f16.f16.f32 "
        "{%0,%1,%2,%3}, {%4,%5,%6,%7}, {%8,%9}, {%0,%1,%2,%3};"
        : "+f"(c[0]), "+f"(c[1]), "+f"(c[2]), "+f"(c[3])
        : "r"(a[0]), "r"(a[1]), "r"(a[2]), "r"(a[3]), "r"(b[0]), "r"(b[1]));
}

__device__ __forceinline__ void ldsm4(uint32_t* r, uint32_t addr) {
    asm volatile(
        "ldmatrix.sync.aligned.m8n8.x4.shared.b16 {%0,%1,%2,%3}, [%4];"
        : "=r"(r[0]), "=r"(r[1]), "=r"(r[2]), "=r"(r[3]) : "r"(addr));
}

__device__ __forceinline__ void cpa16(uint32_t dst, const void* src) {
    asm volatile("cp.async.cg.shared.global [%0], [%1], 16;"
                 :: "r"(dst), "l"(__cvta_generic_to_global(src)) : "memory");
}

// ---------------------------------------------------------------------------
// Kernel A: fused prep with 8-wide ILP.
// ranges: X-proj 16384 threads (r, kp4) | Y-proj 16384 | W2-pack 8192 (kp, n4)
// ---------------------------------------------------------------------------
__global__ void prep_all(const float* __restrict__ X,
                         const float* __restrict__ Y,
                         const float* __restrict__ W1,
                         const float* __restrict__ b1,
                         const float* __restrict__ W2) {
    int idx = blockIdx.x * blockDim.x + threadIdx.x;
    if (idx < 32768) {                         // X and Y projections
        const int isY = idx >> 14;             // 0: X, 1: Y
        const int e = idx & 16383;
        const int r = e >> 5, kp4 = e & 31;    // kp4: group of 4 kp = 8 k-cols
        const int k0 = kp4 * 8;
        float acc[8];
        if (!isY) {
            #pragma unroll
            for (int u = 0; u < 8; u++) acc[u] = b1[k0 + u];
        } else {
            #pragma unroll
            for (int u = 0; u < 8; u++) acc[u] = 0.f;
        }
        const float* src = isY ? (Y + r * NYD) : (X + r * NXD);
        const float* w1b = W1 + (isY ? NXD * HID : 0) + k0;
        #pragma unroll 4
        for (int t = 0; t < 64; t++) {
            float v = src[t];
            float4 wa = *(const float4*)(w1b + t * HID);
            float4 wb = *(const float4*)(w1b + t * HID + 4);
            acc[0] = fmaf(v, wa.x, acc[0]); acc[1] = fmaf(v, wa.y, acc[1]);
            acc[2] = fmaf(v, wa.z, acc[2]); acc[3] = fmaf(v, wa.w, acc[3]);
            acc[4] = fmaf(v, wb.x, acc[4]); acc[5] = fmaf(v, wb.y, acc[5]);
            acc[6] = fmaf(v, wb.z, acc[6]); acc[7] = fmaf(v, wb.w, acc[7]);
        }
        uint4 o;
        __half2 h0 = __float22half2_rn(make_float2(acc[0], acc[1]));
        __half2 h1 = __float22half2_rn(make_float2(acc[2], acc[3]));
        __half2 h2 = __float22half2_rn(make_float2(acc[4], acc[5]));
        __half2 h3 = __float22half2_rn(make_float2(acc[6], acc[7]));
        o.x = *(uint32_t*)&h0; o.y = *(uint32_t*)&h1;
        o.z = *(uint32_t*)&h2; o.w = *(uint32_t*)&h3;
        uint32_t* dst = isY ? g_yph : g_xph;
        *(uint4*)(dst + r * 128 + kp4 * 4) = o;
    } else {                                   // W2 pack: 8192 threads
        int e = idx - 32768;
        int kp = e >> 6, n4 = e & 63;          // lanes: consecutive n4, same kp
        float4 w0 = *(const float4*)(W2 + (2 * kp) * HID + n4 * 4);
        float4 w1 = *(const float4*)(W2 + (2 * kp + 1) * HID + n4 * 4);
        const float* p0 = (const float*)&w0;
        const float* p1 = (const float*)&w1;
        #pragma unroll
        for (int i = 0; i < 4; i++) {
            __half2 h = __float22half2_rn(make_float2(p0[i], p1[i]));
            g_w2h[(n4 * 4 + i) * 128 + kp] = *(uint32_t*)&h;
        }
    }
}

// ---------------------------------------------------------------------------
// Kernel B: mma.sync fp16 GEMM + fused epilogue + fused exp row-partials.
// CTA: 128 pairs (16 y x 8 x), N=256 in two halves, K=256 in 4 chunks of 64.
// smem (u32): A [0,16896) stride 132 | B [16896,26112) 2 bufs x 4608 stride 36
//             B2S [26112) W3S [26368) PART [26624) ; total 26880 u32 (107.5KB)
// ---------------------------------------------------------------------------
#define SA   132
#define SB   36
#define A_HI 0
#define B_BASE 16896
#define B2S  26112
#define W3S  26368
#define PART 26624
#define SM_U32 26880
#define SM_BYTES (SM_U32 * 4)

__global__ void __launch_bounds__(256, 2)
mlp_mma_kernel(const float* __restrict__ b2,
               const float* __restrict__ W3,
               const float* __restrict__ b3) {
    extern __shared__ __align__(16) uint32_t sm[];
    const int tid = threadIdx.x;
    const int lane = tid & 31, wid = tid >> 5;
    const int lq = lane >> 2, lr = lane & 3;
    const int wm = wid >> 1, wn = wid & 1;
    const int i0 = blockIdx.y * 16, j0 = blockIdx.x * 8;
    const uint32_t sb = smem_u32(sm);

    ((float*)(sm + B2S))[tid] = b2[tid];
    ((float*)(sm + W3S))[tid] = W3[tid];

    // ---- build A = relu(xph[j]+yph[i]) in half2, uint4 granularity ---------
    const __half2 z2 = __float2half2_rn(0.f);
    #pragma unroll
    for (int q = 0; q < 16; q++) {
        int e = tid + q * 256;              // uint4 index: (row, c4) c4 in 0..31
        int row = e >> 5, c4 = e & 31;
        int i = i0 + (row >> 3), j = j0 + (row & 7);
        uint4 xv = *(const uint4*)(g_xph + j * 128 + c4 * 4);
        uint4 yv = *(const uint4*)(g_yph + i * 128 + c4 * 4);
        uint4 o;
        __half2 t0, t1, t2, t3;
        t0 = __hmax2(__hadd2(*(__half2*)&xv.x, *(__half2*)&yv.x), z2);
        t1 = __hmax2(__hadd2(*(__half2*)&xv.y, *(__half2*)&yv.y), z2);
        t2 = __hmax2(__hadd2(*(__half2*)&xv.z, *(__half2*)&yv.z), z2);
        t3 = __hmax2(__hadd2(*(__half2*)&xv.w, *(__half2*)&yv.w), z2);
        o.x = *(uint32_t*)&t0; o.y = *(uint32_t*)&t1;
        o.z = *(uint32_t*)&t2; o.w = *(uint32_t*)&t3;
        *(uint4*)(sm + A_HI + row * SA + c4 * 4) = o;
    }

    // ---- B pipeline: 8 chunks (nh 0..1 x kc 0..3), K=64 each (18KB) --------
    auto load_chunk = [&](int t, int buf) {
        int nh = t >> 2, kc = t & 3;
        uint32_t bbase = B_BASE + buf * 4608;
        #pragma unroll
        for (int q = 0; q < 4; q++) {
            int idx = tid + q * 256;        // 1024 float4: [nl (128)][jj (8)]
            int nl = idx >> 3, jj = idx & 7;
            const uint32_t* src = g_w2h + (nh * 128 + nl) * 128 + kc * 32 + jj * 4;
            uint32_t dst = sb + (bbase + nl * SB + jj * 4) * 4;
            cpa16(dst, src);
        }
        asm volatile("cp.async.commit_group;" ::: "memory");
    };

    load_chunk(0, 0);

    // ---- precomputed ldmatrix lane addresses -------------------------------
    uint32_t aAddr[2];
    {
        int arow = wm * 32 + (lane & 15);
        uint32_t koffb = (lane >> 4) ? 16u : 0u;
        #pragma unroll
        for (int mt = 0; mt < 2; mt++)
            aAddr[mt] = sb + (uint32_t)((A_HI + (arow + mt * 16) * SA)) * 4u + koffb;
    }
    uint32_t bAddr[4];
    {
        int nrow = wn * 64 + (lane & 7) + ((lane >> 4) ? 8 : 0);
        uint32_t koffb = ((lane >> 3) & 1) ? 16u : 0u;
        #pragma unroll
        for (int ntp = 0; ntp < 4; ntp++)
            bAddr[ntp] = sb + (uint32_t)(B_BASE + (nrow + ntp * 16) * SB) * 4u + koffb;
    }

    float c[2][8][4];
    #pragma unroll
    for (int mt = 0; mt < 2; mt++)
        #pragma unroll
        for (int nt = 0; nt < 8; nt++)
            #pragma unroll
            for (int q = 0; q < 4; q++) c[mt][nt][q] = 0.f;

    float pr[2][2] = {{0.f, 0.f}, {0.f, 0.f}};
    const float* b2s = (const float*)(sm + B2S);
    const float* w3s = (const float*)(sm + W3S);

    for (int t = 0; t < 8; t++) {
        const int buf = t & 1;
        const int nh = t >> 2, kc = t & 3;
        if (t < 7) {
            load_chunk(t + 1, buf ^ 1);
            asm volatile("cp.async.wait_group 1;" ::: "memory");
        } else {
            asm volatile("cp.async.wait_group 0;" ::: "memory");
        }
        __syncthreads();

        const uint32_t bufOff = (uint32_t)buf * 4608u * 4u;

        #pragma unroll
        for (int s = 0; s < 4; s++) {
            const uint32_t akb = (uint32_t)(kc * 32 + s * 8) * 4u;
            const uint32_t bkb = bufOff + (uint32_t)s * 32u;

            uint32_t ah[2][4];
            ldsm4(ah[0], aAddr[0] + akb);
            ldsm4(ah[1], aAddr[1] + akb);
            #pragma unroll
            for (int ntp = 0; ntp < 4; ntp++) {
                uint32_t bh[4];
                ldsm4(bh, bAddr[ntp] + bkb);
                #pragma unroll
                for (int g = 0; g < 2; g++) {
                    int nt = ntp * 2 + g;
                    mma_f16(c[0][nt], ah[0], bh + g * 2);
                    mma_f16(c[1][nt], ah[1], bh + g * 2);
                }
            }
        }

        if (kc == 3) {                       // N-half done -> partial epilogue
            #pragma unroll
            for (int mt = 0; mt < 2; mt++)
                #pragma unroll
                for (int nt = 0; nt < 8; nt++)
                    #pragma unroll
                    for (int q = 0; q < 4; q++) {
                        int col = nh * 128 + wn * 64 + nt * 8 + lr * 2 + (q & 1);
                        float h = fmaxf(c[mt][nt][q] + b2s[col], 0.f);
                        pr[mt][q >> 1] = fmaf(h, w3s[col], pr[mt][q >> 1]);
                        c[mt][nt][q] = 0.f;
                    }
        }
        __syncthreads();
    }

    // ---- reduce partial dots over lane%4 group, combine warps --------------
    #pragma unroll
    for (int mt = 0; mt < 2; mt++)
        #pragma unroll
        for (int rh = 0; rh < 2; rh++) {
            float p = pr[mt][rh];
            p += __shfl_xor_sync(0xffffffffu, p, 1);
            p += __shfl_xor_sync(0xffffffffu, p, 2);
            if (lr == 0) {
                int row = wm * 32 + mt * 16 + rh * 8 + lq;
                ((float*)(sm + PART))[row * 2 + wn] = p;
            }
        }
    __syncthreads();

    // ---- scores -> fused exp row-partials + diag ---------------------------
    if (tid < 128) {                          // warps 0-3, fully active
        const float* part = (const float*)(sm + PART);
        float sc = part[tid * 2] + part[tid * 2 + 1] + b3[0];
        int i = i0 + (tid >> 3), j = j0 + (tid & 7);
        if (i == j) g_diag[i] = sc;
        float e = expf(sc);                   // scores are O(1): no max shift
        e += __shfl_xor_sync(0xffffffffu, e, 1);
        e += __shfl_xor_sync(0xffffffffu, e, 2);
        e += __shfl_xor_sync(0xffffffffu, e, 4);
        if ((tid & 7) == 0)
            g_rowpart[i * 64 + blockIdx.x] = e;   // transposed: row-major
    }
}

// ---------------------------------------------------------------------------
// Kernel C: final scalar — vectorized row reduce (MLP 16), then tree
// ---------------------------------------------------------------------------
__global__ void final_kernel(float* __restrict__ out) {
    __shared__ float rd[512];
    __shared__ float rl[512];
    const int t = threadIdx.x;                // 512
    const float4* rp = (const float4*)(g_rowpart + t * 64);
    float s0 = 0.f, s1 = 0.f, s2 = 0.f, s3 = 0.f;
    #pragma unroll
    for (int q = 0; q < 16; q++) {
        float4 v = rp[q];
        s0 += v.x; s1 += v.y; s2 += v.z; s3 += v.w;
    }
    rl[t] = logf((s0 + s1) + (s2 + s3));
    rd[t] = g_diag[t];
    __syncthreads();
    for (int o = 256; o; o >>= 1) {
        if (t < o) { rd[t] += rd[t + o]; rl[t] += rl[t + o]; }
        __syncthreads();
    }
    if (t == 0) {
        float mi = logf((float)BB) + rd[0] / (float)BB - rl[0] / (float)BB;
        out[0] = -mi;
    }
}

// ---------------------------------------------------------------------------
extern "C" void kernel_launch(void* const* d_in, const int* in_sizes, int n_in,
                              void* d_out, int out_size) {
    const float* dataX = (const float*)d_in[0];
    const float* dataY = (const float*)d_in[1];
    const float* W1    = (const float*)d_in[2];
    const float* b1    = (const float*)d_in[3];
    const float* W2    = (const float*)d_in[4];
    const float* b2    = (const float*)d_in[5];
    const float* W3    = (const float*)d_in[6];
    const float* b3    = (const float*)d_in[7];
    float* out = (float*)d_out;

    cudaFuncSetAttribute(mlp_mma_kernel,
                         cudaFuncAttributeMaxDynamicSharedMemorySize, SM_BYTES);

    prep_all<<<160, 256>>>(dataX, dataY, W1, b1, W2);

    dim3 grid(BB / 8, BB / 16);   // 64 x-tiles x 32 y-tiles
    mlp_mma_kernel<<<grid, 256, SM_BYTES>>>(b2, W3, b3);

    final_kernel<<<1, BB>>>(out);
}

// round 14
// speedup vs baseline: 1.0008x; 1.0008x over previous
#include <cuda_runtime.h>
#include <cuda_fp16.h>
#include <math.h>
#include <stdint.h>

#define BB 512
#define NXD 64
#define NYD 64
#define HID 256

// ---------------- device scratch ---------------------------------------------
__device__ __align__(16) uint32_t g_xph[BB * 128];   // fp16 pairs: b1 + X@W1[:64]
__device__ __align__(16) uint32_t g_yph[BB * 128];   // fp16 pairs: Y@W1[64:]
__device__ __align__(16) uint32_t g_w2h[HID * 128];  // W2^T fp16 pairs [n][kp]
__device__ __align__(16) float g_rowpart[BB * 64];   // [row i][bx] sum of exp
__device__ float g_diag[BB];

// ---------------- helpers ----------------------------------------------------
__device__ __forceinline__ uint32_t smem_u32(const void* p) {
    uint32_t a;
    asm("{ .reg .u64 t; cvta.to.shared.u64 t, %1; cvt.u32.u64 %0, t; }"
        : "=r"(a) : "l"(p));
    return a;
}

__device__ __forceinline__ void mma_f16(float* c, const uint32_t* a,
                                        const uint32_t* b) {
    asm volatile(
        "mma.sync.aligned.m16n8k16.row.col.f32.f16.f16.f32 "
        "{%0,%1,%2,%3}, {%4,%5,%6,%7}, {%8,%9}, {%0,%1,%2,%3};"
        : "+f"(c[0]), "+f"(c[1]), "+f"(c[2]), "+f"(c[3])
        : "r"(a[0]), "r"(a[1]), "r"(a[2]), "r"(a[3]), "r"(b[0]), "r"(b[1]));
}

__device__ __forceinline__ void ldsm4(uint32_t* r, uint32_t addr) {
    asm volatile(
        "ldmatrix.sync.aligned.m8n8.x4.shared.b16 {%0,%1,%2,%3}, [%4];"
        : "=r"(r[0]), "=r"(r[1]), "=r"(r[2]), "=r"(r[3]) : "r"(addr));
}

__device__ __forceinline__ void cpa16(uint32_t dst, const void* src) {
    asm volatile("cp.async.cg.shared.global [%0], [%1], 16;"
                 :: "r"(dst), "l"(__cvta_generic_to_global(src)) : "memory");
}

// ---------------------------------------------------------------------------
// Kernel A: fused prep — 8-wide ILP AND k-split x4 for occupancy.
// X-proj: 65536 threads (16384 groups x 4 k-slices), Y-proj: 65536,
// W2-pack: 8192. Total 139264 -> 544 blocks.
// ---------------------------------------------------------------------------
__global__ void prep_all(const float* __restrict__ X,
                         const float* __restrict__ Y,
                         const float* __restrict__ W1,
                         const float* __restrict__ b1,
                         const float* __restrict__ W2) {
    int idx = blockIdx.x * blockDim.x + threadIdx.x;
    if (idx < 131072) {                        // X and Y projections
        const int isY = idx >> 16;             // 0: X, 1: Y
        const int e = idx & 65535;
        const int g = e >> 2, t = e & 3;       // group, k-slice
        const int r = g >> 5, kp4 = g & 31;
        const int k0 = kp4 * 8;
        float acc[8];
        if (!isY && t == 0) {
            #pragma unroll
            for (int u = 0; u < 8; u++) acc[u] = b1[k0 + u];
        } else {
            #pragma unroll
            for (int u = 0; u < 8; u++) acc[u] = 0.f;
        }
        const float* src = (isY ? Y : X) + r * 64 + t * 16;
        const float* w1b = W1 + (isY ? NXD * HID : 0) + (t * 16) * HID + k0;
        #pragma unroll 4
        for (int s = 0; s < 16; s++) {
            float v = src[s];
            float4 wa = *(const float4*)(w1b + s * HID);
            float4 wb = *(const float4*)(w1b + s * HID + 4);
            acc[0] = fmaf(v, wa.x, acc[0]); acc[1] = fmaf(v, wa.y, acc[1]);
            acc[2] = fmaf(v, wa.z, acc[2]); acc[3] = fmaf(v, wa.w, acc[3]);
            acc[4] = fmaf(v, wb.x, acc[4]); acc[5] = fmaf(v, wb.y, acc[5]);
            acc[6] = fmaf(v, wb.z, acc[6]); acc[7] = fmaf(v, wb.w, acc[7]);
        }
        // combine 4 k-slices (lane bits 0-1)
        #pragma unroll
        for (int u = 0; u < 8; u++) {
            acc[u] += __shfl_xor_sync(0xffffffffu, acc[u], 1);
            acc[u] += __shfl_xor_sync(0xffffffffu, acc[u], 2);
        }
        if (t == 0) {
            uint4 o;
            __half2 h0 = __float22half2_rn(make_float2(acc[0], acc[1]));
            __half2 h1 = __float22half2_rn(make_float2(acc[2], acc[3]));
            __half2 h2 = __float22half2_rn(make_float2(acc[4], acc[5]));
            __half2 h3 = __float22half2_rn(make_float2(acc[6], acc[7]));
            o.x = *(uint32_t*)&h0; o.y = *(uint32_t*)&h1;
            o.z = *(uint32_t*)&h2; o.w = *(uint32_t*)&h3;
            uint32_t* dst = isY ? g_yph : g_xph;
            *(uint4*)(dst + r * 128 + kp4 * 4) = o;
        }
    } else if (idx < 139264) {                 // W2 pack: 8192 threads
        int e = idx - 131072;
        int kp = e >> 6, n4 = e & 63;          // lanes: consecutive n4, same kp
        float4 w0 = *(const float4*)(W2 + (2 * kp) * HID + n4 * 4);
        float4 w1 = *(const float4*)(W2 + (2 * kp + 1) * HID + n4 * 4);
        const float* p0 = (const float*)&w0;
        const float* p1 = (const float*)&w1;
        #pragma unroll
        for (int i = 0; i < 4; i++) {
            __half2 h = __float22half2_rn(make_float2(p0[i], p1[i]));
            g_w2h[(n4 * 4 + i) * 128 + kp] = *(uint32_t*)&h;
        }
    }
}

// ---------------------------------------------------------------------------
// Kernel B: mma.sync fp16 GEMM + fused epilogue + fused exp row-partials.
// CTA: 128 pairs (16 y x 8 x), N=256 in two halves, K=256 in 4 chunks of 64.
// smem (u32): A [0,16896) stride 132 | B [16896,26112) 2 bufs x 4608 stride 36
//             B2S [26112) W3S [26368) PART [26624) ; total 26880 u32 (107.5KB)
// ---------------------------------------------------------------------------
#define SA   132
#define SB   36
#define A_HI 0
#define B_BASE 16896
#define B2S  26112
#define W3S  26368
#define PART 26624
#define SM_U32 26880
#define SM_BYTES (SM_U32 * 4)

__global__ void __launch_bounds__(256, 2)
mlp_mma_kernel(const float* __restrict__ b2,
               const float* __restrict__ W3,
               const float* __restrict__ b3) {
    extern __shared__ __align__(16) uint32_t sm[];
    const int tid = threadIdx.x;
    const int lane = tid & 31, wid = tid >> 5;
    const int lq = lane >> 2, lr = lane & 3;
    const int wm = wid >> 1, wn = wid & 1;
    const int i0 = blockIdx.y * 16, j0 = blockIdx.x * 8;
    const uint32_t sb = smem_u32(sm);

    ((float*)(sm + B2S))[tid] = b2[tid];
    ((float*)(sm + W3S))[tid] = W3[tid];

    // ---- build A = relu(xph[j]+yph[i]) in half2, uint4 granularity ---------
    const __half2 z2 = __float2half2_rn(0.f);
    #pragma unroll
    for (int q = 0; q < 16; q++) {
        int e = tid + q * 256;              // uint4 index: (row, c4) c4 in 0..31
        int row = e >> 5, c4 = e & 31;
        int i = i0 + (row >> 3), j = j0 + (row & 7);
        uint4 xv = *(const uint4*)(g_xph + j * 128 + c4 * 4);
        uint4 yv = *(const uint4*)(g_yph + i * 128 + c4 * 4);
        uint4 o;
        __half2 t0, t1, t2, t3;
        t0 = __hmax2(__hadd2(*(__half2*)&xv.x, *(__half2*)&yv.x), z2);
        t1 = __hmax2(__hadd2(*(__half2*)&xv.y, *(__half2*)&yv.y), z2);
        t2 = __hmax2(__hadd2(*(__half2*)&xv.z, *(__half2*)&yv.z), z2);
        t3 = __hmax2(__hadd2(*(__half2*)&xv.w, *(__half2*)&yv.w), z2);
        o.x = *(uint32_t*)&t0; o.y = *(uint32_t*)&t1;
        o.z = *(uint32_t*)&t2; o.w = *(uint32_t*)&t3;
        *(uint4*)(sm + A_HI + row * SA + c4 * 4) = o;
    }

    // ---- B pipeline: 8 chunks (nh 0..1 x kc 0..3), K=64 each (18KB) --------
    auto load_chunk = [&](int t, int buf) {
        int nh = t >> 2, kc = t & 3;
        uint32_t bbase = B_BASE + buf * 4608;
        #pragma unroll
        for (int q = 0; q < 4; q++) {
            int idx = tid + q * 256;        // 1024 float4: [nl (128)][jj (8)]
            int nl = idx >> 3, jj = idx & 7;
            const uint32_t* src = g_w2h + (nh * 128 + nl) * 128 + kc * 32 + jj * 4;
            uint32_t dst = sb + (bbase + nl * SB + jj * 4) * 4;
            cpa16(dst, src);
        }
        asm volatile("cp.async.commit_group;" ::: "memory");
    };

    load_chunk(0, 0);

    // ---- precomputed ldmatrix lane addresses -------------------------------
    uint32_t aAddr[2];
    {
        int arow = wm * 32 + (lane & 15);
        uint32_t koffb = (lane >> 4) ? 16u : 0u;
        #pragma unroll
        for (int mt = 0; mt < 2; mt++)
            aAddr[mt] = sb + (uint32_t)((A_HI + (arow + mt * 16) * SA)) * 4u + koffb;
    }
    uint32_t bAddr[4];
    {
        int nrow = wn * 64 + (lane & 7) + ((lane >> 4) ? 8 : 0);
        uint32_t koffb = ((lane >> 3) & 1) ? 16u : 0u;
        #pragma unroll
        for (int ntp = 0; ntp < 4; ntp++)
            bAddr[ntp] = sb + (uint32_t)(B_BASE + (nrow + ntp * 16) * SB) * 4u + koffb;
    }

    float c[2][8][4];
    #pragma unroll
    for (int mt = 0; mt < 2; mt++)
        #pragma unroll
        for (int nt = 0; nt < 8; nt++)
            #pragma unroll
            for (int q = 0; q < 4; q++) c[mt][nt][q] = 0.f;

    float pr[2][2] = {{0.f, 0.f}, {0.f, 0.f}};
    const float* b2s = (const float*)(sm + B2S);
    const float* w3s = (const float*)(sm + W3S);

    for (int t = 0; t < 8; t++) {
        const int buf = t & 1;
        const int nh = t >> 2, kc = t & 3;
        if (t < 7) {
            load_chunk(t + 1, buf ^ 1);
            asm volatile("cp.async.wait_group 1;" ::: "memory");
        } else {
            asm volatile("cp.async.wait_group 0;" ::: "memory");
        }
        __syncthreads();

        const uint32_t bufOff = (uint32_t)buf * 4608u * 4u;

        #pragma unroll
        for (int s = 0; s < 4; s++) {
            const uint32_t akb = (uint32_t)(kc * 32 + s * 8) * 4u;
            const uint32_t bkb = bufOff + (uint32_t)s * 32u;

            uint32_t ah[2][4];
            ldsm4(ah[0], aAddr[0] + akb);
            ldsm4(ah[1], aAddr[1] + akb);
            #pragma unroll
            for (int ntp = 0; ntp < 4; ntp++) {
                uint32_t bh[4];
                ldsm4(bh, bAddr[ntp] + bkb);
                #pragma unroll
                for (int g = 0; g < 2; g++) {
                    int nt = ntp * 2 + g;
                    mma_f16(c[0][nt], ah[0], bh + g * 2);
                    mma_f16(c[1][nt], ah[1], bh + g * 2);
                }
            }
        }

        if (kc == 3) {                       // N-half done -> partial epilogue
            #pragma unroll
            for (int mt = 0; mt < 2; mt++)
                #pragma unroll
                for (int nt = 0; nt < 8; nt++)
                    #pragma unroll
                    for (int q = 0; q < 4; q++) {
                        int col = nh * 128 + wn * 64 + nt * 8 + lr * 2 + (q & 1);
                        float h = fmaxf(c[mt][nt][q] + b2s[col], 0.f);
                        pr[mt][q >> 1] = fmaf(h, w3s[col], pr[mt][q >> 1]);
                        c[mt][nt][q] = 0.f;
                    }
        }
        __syncthreads();
    }

    // ---- reduce partial dots over lane%4 group, combine warps --------------
    #pragma unroll
    for (int mt = 0; mt < 2; mt++)
        #pragma unroll
        for (int rh = 0; rh < 2; rh++) {
            float p = pr[mt][rh];
            p += __shfl_xor_sync(0xffffffffu, p, 1);
            p += __shfl_xor_sync(0xffffffffu, p, 2);
            if (lr == 0) {
                int row = wm * 32 + mt * 16 + rh * 8 + lq;
                ((float*)(sm + PART))[row * 2 + wn] = p;
            }
        }
    __syncthreads();

    // ---- scores -> fused exp row-partials + diag ---------------------------
    if (tid < 128) {                          // warps 0-3, fully active
        const float* part = (const float*)(sm + PART);
        float sc = part[tid * 2] + part[tid * 2 + 1] + b3[0];
        int i = i0 + (tid >> 3), j = j0 + (tid & 7);
        if (i == j) g_diag[i] = sc;
        float e = expf(sc);                   // scores are O(1): no max shift
        e += __shfl_xor_sync(0xffffffffu, e, 1);
        e += __shfl_xor_sync(0xffffffffu, e, 2);
        e += __shfl_xor_sync(0xffffffffu, e, 4);
        if ((tid & 7) == 0)
            g_rowpart[i * 64 + blockIdx.x] = e;   // transposed: row-major
    }
}

// ---------------------------------------------------------------------------
// Kernel C: final scalar — vectorized row reduce (MLP 16), then tree
// ---------------------------------------------------------------------------
__global__ void final_kernel(float* __restrict__ out) {
    __shared__ float rd[512];
    __shared__ float rl[512];
    const int t = threadIdx.x;                // 512
    const float4* rp = (const float4*)(g_rowpart + t * 64);
    float s0 = 0.f, s1 = 0.f, s2 = 0.f, s3 = 0.f;
    #pragma unroll
    for (int q = 0; q < 16; q++) {
        float4 v = rp[q];
        s0 += v.x; s1 += v.y; s2 += v.z; s3 += v.w;
    }
    rl[t] = logf((s0 + s1) + (s2 + s3));
    rd[t] = g_diag[t];
    __syncthreads();
    for (int o = 256; o; o >>= 1) {
        if (t < o) { rd[t] += rd[t + o]; rl[t] += rl[t + o]; }
        __syncthreads();
    }
    if (t == 0) {
        float mi = logf((float)BB) + rd[0] / (float)BB - rl[0] / (float)BB;
        out[0] = -mi;
    }
}

// ---------------------------------------------------------------------------
extern "C" void kernel_launch(void* const* d_in, const int* in_sizes, int n_in,
                              void* d_out, int out_size) {
    const float* dataX = (const float*)d_in[0];
    const float* dataY = (const float*)d_in[1];
    const float* W1    = (const float*)d_in[2];
    const float* b1    = (const float*)d_in[3];
    const float* W2    = (const float*)d_in[4];
    const float* b2    = (const float*)d_in[5];
    const float* W3    = (const float*)d_in[6];
    const float* b3    = (const float*)d_in[7];
    float* out = (float*)d_out;

    cudaFuncSetAttribute(mlp_mma_kernel,
                         cudaFuncAttributeMaxDynamicSharedMemorySize, SM_BYTES);

    prep_all<<<544, 256>>>(dataX, dataY, W1, b1, W2);

    dim3 grid(BB / 8, BB / 16);   // 64 x-tiles x 32 y-tiles
    mlp_mma_kernel<<<grid, 256, SM_BYTES>>>(b2, W3, b3);

    final_kernel<<<1, BB>>>(out);
}

// round 15
// speedup vs baseline: 1.0350x; 1.0342x over previous
#include <cuda_runtime.h>
#include <cuda_fp16.h>
#include <math.h>
#include <stdint.h>

#define BB 512
#define NXD 64
#define NYD 64
#define HID 256

// ---------------- device scratch ---------------------------------------------
__device__ __align__(16) uint32_t g_xph[BB * 128];   // fp16 pairs: b1 + X@W1[:64]
__device__ __align__(16) uint32_t g_yph[BB * 128];   // fp16 pairs: Y@W1[64:]
__device__ __align__(16) uint32_t g_w2h[HID * 128];  // W2^T fp16 pairs [n][kp]
__device__ __align__(16) float g_rowpart[BB * 64];   // [row i][bx] sum of exp
__device__ float g_diag[BB];

// ---------------- helpers ----------------------------------------------------
__device__ __forceinline__ uint32_t smem_u32(const void* p) {
    uint32_t a;
    asm("{ .reg .u64 t; cvta.to.shared.u64 t, %1; cvt.u32.u64 %0, t; }"
        : "=r"(a) : "l"(p));
    return a;
}

__device__ __forceinline__ void mma_f16(float* c, const uint32_t* a,
                                        const uint32_t* b) {
    asm volatile(
        "mma.sync.aligned.m16n8k16.row.col.f32.f16.f16.f32 "
        "{%0,%1,%2,%3}, {%4,%5,%6,%7}, {%8,%9}, {%0,%1,%2,%3};"
        : "+f"(c[0]), "+f"(c[1]), "+f"(c[2]), "+f"(c[3])
        : "r"(a[0]), "r"(a[1]), "r"(a[2]), "r"(a[3]), "r"(b[0]), "r"(b[1]));
}

__device__ __forceinline__ void ldsm4(uint32_t* r, uint32_t addr) {
    asm volatile(
        "ldmatrix.sync.aligned.m8n8.x4.shared.b16 {%0,%1,%2,%3}, [%4];"
        : "=r"(r[0]), "=r"(r[1]), "=r"(r[2]), "=r"(r[3]) : "r"(addr));
}

__device__ __forceinline__ void cpa16(uint32_t dst, const void* src) {
    asm volatile("cp.async.cg.shared.global [%0], [%1], 16;"
                 :: "r"(dst), "l"(__cvta_generic_to_global(src)) : "memory");
}

// ---------------------------------------------------------------------------
// Kernel A: fused prep — R11 projection layout (proven 12.3us) +
// coalesced W2 pack. ranges: X 65536 | Y 65536 | W2 8192 -> 544 blocks.
// ---------------------------------------------------------------------------
__global__ void prep_all(const float* __restrict__ X,
                         const float* __restrict__ Y,
                         const float* __restrict__ W1,
                         const float* __restrict__ b1,
                         const float* __restrict__ W2) {
    int idx = blockIdx.x * blockDim.x + threadIdx.x;
    const int half = BB * 128;
    if (idx < half) {
        int r = idx >> 7, kp = idx & 127;
        float a0 = b1[2 * kp], a1 = b1[2 * kp + 1];
        #pragma unroll 8
        for (int t = 0; t < NXD; t++) {
            float xv = X[r * NXD + t];
            a0 = fmaf(xv, W1[t * HID + 2 * kp], a0);
            a1 = fmaf(xv, W1[t * HID + 2 * kp + 1], a1);
        }
        __half2 h = __float22half2_rn(make_float2(a0, a1));
        g_xph[idx] = *reinterpret_cast<uint32_t*>(&h);
    } else if (idx < 2 * half) {
        int e = idx - half;
        int r = e >> 7, kp = e & 127;
        float a0 = 0.f, a1 = 0.f;
        #pragma unroll 8
        for (int t = 0; t < NYD; t++) {
            float yv = Y[r * NYD + t];
            a0 = fmaf(yv, W1[(NXD + t) * HID + 2 * kp], a0);
            a1 = fmaf(yv, W1[(NXD + t) * HID + 2 * kp + 1], a1);
        }
        __half2 h = __float22half2_rn(make_float2(a0, a1));
        g_yph[e] = *reinterpret_cast<uint32_t*>(&h);
    } else if (idx < 2 * half + 8192) {        // W2 pack, coalesced float4
        int e = idx - 2 * half;
        int kp = e >> 6, n4 = e & 63;
        float4 w0 = *(const float4*)(W2 + (2 * kp) * HID + n4 * 4);
        float4 w1 = *(const float4*)(W2 + (2 * kp + 1) * HID + n4 * 4);
        const float* p0 = (const float*)&w0;
        const float* p1 = (const float*)&w1;
        #pragma unroll
        for (int i = 0; i < 4; i++) {
            __half2 h = __float22half2_rn(make_float2(p0[i], p1[i]));
            g_w2h[(n4 * 4 + i) * 128 + kp] = *(uint32_t*)&h;
        }
    }
}

// ---------------------------------------------------------------------------
// Kernel B: mma.sync fp16 GEMM + fused epilogue + fused exp row-partials.
// CTA: 128 pairs (16 y x 8 x), N=256 in two halves, K=256 in 4 chunks of 64.
// ONE barrier per chunk: wait_group 0 -> syncthreads -> prefetch -> compute.
// smem (u32): A [0,16896) stride 132 | B [16896,26112) 2 bufs x 4608 stride 36
//             B2S [26112) W3S [26368) PART [26624) ; total 26880 u32 (107.5KB)
// ---------------------------------------------------------------------------
#define SA   132
#define SB   36
#define A_HI 0
#define B_BASE 16896
#define B2S  26112
#define W3S  26368
#define PART 26624
#define SM_U32 26880
#define SM_BYTES (SM_U32 * 4)

__global__ void __launch_bounds__(256, 2)
mlp_mma_kernel(const float* __restrict__ b2,
               const float* __restrict__ W3,
               const float* __restrict__ b3) {
    extern __shared__ __align__(16) uint32_t sm[];
    const int tid = threadIdx.x;
    const int lane = tid & 31, wid = tid >> 5;
    const int lq = lane >> 2, lr = lane & 3;
    const int wm = wid >> 1, wn = wid & 1;
    const int i0 = blockIdx.y * 16, j0 = blockIdx.x * 8;
    const uint32_t sb = smem_u32(sm);

    ((float*)(sm + B2S))[tid] = b2[tid];
    ((float*)(sm + W3S))[tid] = W3[tid];

    // ---- B pipeline loader (chunk = 2 nh x 4 kc, K=64, 18KB) ---------------
    auto load_chunk = [&](int t, int buf) {
        int nh = t >> 2, kc = t & 3;
        uint32_t bbase = B_BASE + buf * 4608;
        #pragma unroll
        for (int q = 0; q < 4; q++) {
            int idx = tid + q * 256;        // 1024 float4: [nl (128)][jj (8)]
            int nl = idx >> 3, jj = idx & 7;
            const uint32_t* src = g_w2h + (nh * 128 + nl) * 128 + kc * 32 + jj * 4;
            uint32_t dst = sb + (bbase + nl * SB + jj * 4) * 4;
            cpa16(dst, src);
        }
        asm volatile("cp.async.commit_group;" ::: "memory");
    };

    load_chunk(0, 0);   // prefetch chunk 0 before the A-build (overlap)

    // ---- build A = relu(xph[j]+yph[i]) in half2, uint4 granularity ---------
    const __half2 z2 = __float2half2_rn(0.f);
    #pragma unroll
    for (int q = 0; q < 16; q++) {
        int e = tid + q * 256;              // uint4 index: (row, c4) c4 in 0..31
        int row = e >> 5, c4 = e & 31;
        int i = i0 + (row >> 3), j = j0 + (row & 7);
        uint4 xv = *(const uint4*)(g_xph + j * 128 + c4 * 4);
        uint4 yv = *(const uint4*)(g_yph + i * 128 + c4 * 4);
        uint4 o;
        __half2 t0, t1, t2, t3;
        t0 = __hmax2(__hadd2(*(__half2*)&xv.x, *(__half2*)&yv.x), z2);
        t1 = __hmax2(__hadd2(*(__half2*)&xv.y, *(__half2*)&yv.y), z2);
        t2 = __hmax2(__hadd2(*(__half2*)&xv.z, *(__half2*)&yv.z), z2);
        t3 = __hmax2(__hadd2(*(__half2*)&xv.w, *(__half2*)&yv.w), z2);
        o.x = *(uint32_t*)&t0; o.y = *(uint32_t*)&t1;
        o.z = *(uint32_t*)&t2; o.w = *(uint32_t*)&t3;
        *(uint4*)(sm + A_HI + row * SA + c4 * 4) = o;
    }

    // ---- precomputed ldmatrix lane addresses -------------------------------
    uint32_t aAddr[2];
    {
        int arow = wm * 32 + (lane & 15);
        uint32_t koffb = (lane >> 4) ? 16u : 0u;
        #pragma unroll
        for (int mt = 0; mt < 2; mt++)
            aAddr[mt] = sb + (uint32_t)((A_HI + (arow + mt * 16) * SA)) * 4u + koffb;
    }
    uint32_t bAddr[4];
    {
        int nrow = wn * 64 + (lane & 7) + ((lane >> 4) ? 8 : 0);
        uint32_t koffb = ((lane >> 3) & 1) ? 16u : 0u;
        #pragma unroll
        for (int ntp = 0; ntp < 4; ntp++)
            bAddr[ntp] = sb + (uint32_t)(B_BASE + (nrow + ntp * 16) * SB) * 4u + koffb;
    }

    float c[2][8][4];
    #pragma unroll
    for (int mt = 0; mt < 2; mt++)
        #pragma unroll
        for (int nt = 0; nt < 8; nt++)
            #pragma unroll
            for (int q = 0; q < 4; q++) c[mt][nt][q] = 0.f;

    float pr[2][2] = {{0.f, 0.f}, {0.f, 0.f}};
    const float* b2s = (const float*)(sm + B2S);
    const float* w3s = (const float*)(sm + W3S);

    for (int t = 0; t < 8; t++) {
        const int buf = t & 1;
        const int nh = t >> 2, kc = t & 3;
        // chunk t is the only outstanding cp.async group here
        asm volatile("cp.async.wait_group 0;" ::: "memory");
        __syncthreads();   // publishes chunk t; proves buf^1 readers (iter t-1) done
        if (t < 7) load_chunk(t + 1, buf ^ 1);

        const uint32_t bufOff = (uint32_t)buf * 4608u * 4u;

        #pragma unroll
        for (int s = 0; s < 4; s++) {
            const uint32_t akb = (uint32_t)(kc * 32 + s * 8) * 4u;
            const uint32_t bkb = bufOff + (uint32_t)s * 32u;

            uint32_t ah[2][4];
            ldsm4(ah[0], aAddr[0] + akb);
            ldsm4(ah[1], aAddr[1] + akb);
            #pragma unroll
            for (int ntp = 0; ntp < 4; ntp++) {
                uint32_t bh[4];
                ldsm4(bh, bAddr[ntp] + bkb);
                #pragma unroll
                for (int g = 0; g < 2; g++) {
                    int nt = ntp * 2 + g;
                    mma_f16(c[0][nt], ah[0], bh + g * 2);
                    mma_f16(c[1][nt], ah[1], bh + g * 2);
                }
            }
        }

        if (kc == 3) {                       // N-half done -> partial epilogue
            #pragma unroll
            for (int mt = 0; mt < 2; mt++)
                #pragma unroll
                for (int nt = 0; nt < 8; nt++)
                    #pragma unroll
                    for (int q = 0; q < 4; q++) {
                        int col = nh * 128 + wn * 64 + nt * 8 + lr * 2 + (q & 1);
                        float h = fmaxf(c[mt][nt][q] + b2s[col], 0.f);
                        pr[mt][q >> 1] = fmaf(h, w3s[col], pr[mt][q >> 1]);
                        c[mt][nt][q] = 0.f;
                    }
        }
    }

    // ---- reduce partial dots over lane%4 group, combine warps --------------
    #pragma unroll
    for (int mt = 0; mt < 2; mt++)
        #pragma unroll
        for (int rh = 0; rh < 2; rh++) {
            float p = pr[mt][rh];
            p += __shfl_xor_sync(0xffffffffu, p, 1);
            p += __shfl_xor_sync(0xffffffffu, p, 2);
            if (lr == 0) {
                int row = wm * 32 + mt * 16 + rh * 8 + lq;
                ((float*)(sm + PART))[row * 2 + wn] = p;
            }
        }
    __syncthreads();

    // ---- scores -> fused exp row-partials + diag ---------------------------
    if (tid < 128) {                          // warps 0-3, fully active
        const float* part = (const float*)(sm + PART);
        float sc = part[tid * 2] + part[tid * 2 + 1] + b3[0];
        int i = i0 + (tid >> 3), j = j0 + (tid & 7);
        if (i == j) g_diag[i] = sc;
        float e = expf(sc);                   // scores are O(1): no max shift
        e += __shfl_xor_sync(0xffffffffu, e, 1);
        e += __shfl_xor_sync(0xffffffffu, e, 2);
        e += __shfl_xor_sync(0xffffffffu, e, 4);
        if ((tid & 7) == 0)
            g_rowpart[i * 64 + blockIdx.x] = e;   // transposed: row-major
    }
}

// ---------------------------------------------------------------------------
// Kernel C: final scalar — vectorized row reduce (MLP 16), then tree
// ---------------------------------------------------------------------------
__global__ void final_kernel(float* __restrict__ out) {
    __shared__ float rd[512];
    __shared__ float rl[512];
    const int t = threadIdx.x;                // 512
    const float4* rp = (const float4*)(g_rowpart + t * 64);
    float s0 = 0.f, s1 = 0.f, s2 = 0.f, s3 = 0.f;
    #pragma unroll
    for (int q = 0; q < 16; q++) {
        float4 v = rp[q];
        s0 += v.x; s1 += v.y; s2 += v.z; s3 += v.w;
    }
    rl[t] = logf((s0 + s1) + (s2 + s3));
    rd[t] = g_diag[t];
    __syncthreads();
    for (int o = 256; o; o >>= 1) {
        if (t < o) { rd[t] += rd[t + o]; rl[t] += rl[t + o]; }
        __syncthreads();
    }
    if (t == 0) {
        float mi = logf((float)BB) + rd[0] / (float)BB - rl[0] / (float)BB;
        out[0] = -mi;
    }
}

// ---------------------------------------------------------------------------
extern "C" void kernel_launch(void* const* d_in, const int* in_sizes, int n_in,
                              void* d_out, int out_size) {
    const float* dataX = (const float*)d_in[0];
    const float* dataY = (const float*)d_in[1];
    const float* W1    = (const float*)d_in[2];
    const float* b1    = (const float*)d_in[3];
    const float* W2    = (const float*)d_in[4];
    const float* b2    = (const float*)d_in[5];
    const float* W3    = (const float*)d_in[6];
    const float* b3    = (const float*)d_in[7];
    float* out = (float*)d_out;

    cudaFuncSetAttribute(mlp_mma_kernel,
                         cudaFuncAttributeMaxDynamicSharedMemorySize, SM_BYTES);

    prep_all<<<544, 256>>>(dataX, dataY, W1, b1, W2);

    dim3 grid(BB / 8, BB / 16);   // 64 x-tiles x 32 y-tiles
    mlp_mma_kernel<<<grid, 256, SM_BYTES>>>(b2, W3, b3);

    final_kernel<<<1, BB>>>(out);
}